// round 1
// baseline (speedup 1.0000x reference)
#include <cuda_runtime.h>
#include <math.h>

#define NB 2
#define NS 2048
#define ND 2048
#define NH 16
#define HD 128
#define NM (NB*NS)   // 4096 rows

// ---- scratch (static device arrays; no allocation allowed) ----
__device__ float g_q[NM*ND];
__device__ float g_k[NM*ND];
__device__ float g_v[NM*ND];
__device__ float g_att[NM*ND];

// ---- packed f32x2 helpers (Blackwell dual-rate fp32) ----
#define FMA2(c,a,b)   asm("fma.rn.f32x2 %0, %1, %2, %0;" : "+l"(c) : "l"(a), "l"(b))
#define PACK2(p,lo,hi) asm("mov.b64 %0, {%1, %2};" : "=l"(p) : "f"(lo), "f"(hi))
#define UNPACK2(lo,hi,p) asm("mov.b64 {%0, %1}, %2;" : "=f"(lo), "=f"(hi) : "l"(p))

// ============================================================================
// GEMM: C[M,N] = A[M,K] @ W[K,N] + bias,  fp32 with packed f32x2 FMAs.
// CTA tile 128m x 256n, 256 threads, per-thread 8m x 16n (as 64 f32x2 accums).
// n-cols per thread are 4 groups of 4 (col = g*64 + tx*4) for conflict-free
// 256B-contiguous LDS.128 reads of Bs.
// ============================================================================
__global__ __launch_bounds__(256)
void gemm_bias_kernel(const float* __restrict__ A, const float* __restrict__ W,
                      const float* __restrict__ bias, float* __restrict__ C,
                      int M, int N, int K)
{
    __shared__ float As[8][132];
    __shared__ float Bs[8][260];
    const int tid = threadIdx.x;
    const int tx = tid & 15;     // n-thread 0..15
    const int ty = tid >> 4;     // m-thread 0..15
    const int m0 = blockIdx.y * 128;
    const int n0 = blockIdx.x * 256;

    unsigned long long acc[8][8];
#pragma unroll
    for (int i = 0; i < 8; i++)
#pragma unroll
        for (int j = 0; j < 8; j++) acc[i][j] = 0ULL;

    // A loader: 128 rows x 8 k; each thread one float4
    const int lm = tid >> 1;
    const int lk = (tid & 1) * 4;
    const float* Ap = A + (long long)(m0 + lm) * K + lk;
    // B loader: 8 rows x 256 cols; each thread two float4 (rows bkk, bkk+4)
    const int bkk = tid >> 6;            // 0..3
    const int bc4 = (tid & 63) * 4;      // 0..252
    const float* Bp = W + (long long)bkk * N + n0 + bc4;

    float4 av  = *(const float4*)(Ap);
    float4 bv0 = *(const float4*)(Bp);
    float4 bv1 = *(const float4*)(Bp + 4ll * N);

    for (int k0 = 0; k0 < K; k0 += 8) {
        As[lk+0][lm] = av.x; As[lk+1][lm] = av.y;
        As[lk+2][lm] = av.z; As[lk+3][lm] = av.w;
        *(float4*)&Bs[bkk  ][bc4] = bv0;
        *(float4*)&Bs[bkk+4][bc4] = bv1;
        __syncthreads();
        if (k0 + 8 < K) {   // software-pipeline next global tile
            av  = *(const float4*)(Ap + k0 + 8);
            bv0 = *(const float4*)(Bp + (long long)(k0+8)  * N);
            bv1 = *(const float4*)(Bp + (long long)(k0+12) * N);
        }
#pragma unroll
        for (int kk = 0; kk < 8; kk++) {
            float4 a0 = *(const float4*)&As[kk][ty*8];
            float4 a1 = *(const float4*)&As[kk][ty*8+4];
            float4 b0 = *(const float4*)&Bs[kk][      tx*4];
            float4 b1 = *(const float4*)&Bs[kk][ 64 + tx*4];
            float4 b2 = *(const float4*)&Bs[kk][128 + tx*4];
            float4 b3 = *(const float4*)&Bs[kk][192 + tx*4];
            unsigned long long ap[8], bp[8];
            PACK2(ap[0], a0.x, a0.x); PACK2(ap[1], a0.y, a0.y);
            PACK2(ap[2], a0.z, a0.z); PACK2(ap[3], a0.w, a0.w);
            PACK2(ap[4], a1.x, a1.x); PACK2(ap[5], a1.y, a1.y);
            PACK2(ap[6], a1.z, a1.z); PACK2(ap[7], a1.w, a1.w);
            PACK2(bp[0], b0.x, b0.y); PACK2(bp[1], b0.z, b0.w);
            PACK2(bp[2], b1.x, b1.y); PACK2(bp[3], b1.z, b1.w);
            PACK2(bp[4], b2.x, b2.y); PACK2(bp[5], b2.z, b2.w);
            PACK2(bp[6], b3.x, b3.y); PACK2(bp[7], b3.z, b3.w);
#pragma unroll
            for (int i = 0; i < 8; i++)
#pragma unroll
                for (int j = 0; j < 8; j++)
                    FMA2(acc[i][j], ap[i], bp[j]);
        }
        __syncthreads();
    }

#pragma unroll
    for (int i = 0; i < 8; i++) {
        float* Cp = C + (long long)(m0 + ty*8 + i) * N + n0;
#pragma unroll
        for (int g = 0; g < 4; g++) {
            float x0,x1,x2,x3;
            UNPACK2(x0, x1, acc[i][2*g]);
            UNPACK2(x2, x3, acc[i][2*g+1]);
            int col = g*64 + tx*4;
            const float* bb = bias + n0 + col;
            float4 r;
            r.x = x0 + bb[0]; r.y = x1 + bb[1];
            r.z = x2 + bb[2]; r.w = x3 + bb[3];
            *(float4*)(Cp + col) = r;
        }
    }
}

// ============================================================================
// RoPE in place on [NM, ND] buffer: per head of 128 dims, pairs (i, i+64).
// ============================================================================
__global__ void rope_kernel(float* __restrict__ X)
{
    int idx = blockIdx.x * blockDim.x + threadIdx.x;  // NM * NH * 64
    int i   = idx & 63;
    int h   = (idx >> 6) & (NH - 1);
    int row = idx >> 10;
    int s   = row & (NS - 1);
    float inv = powf(10000.0f, -(float)i / 64.0f);
    float ang = (float)s * inv;
    float sn, cs;
    sincosf(ang, &sn, &cs);
    float* p = X + (long long)row * ND + h * HD + i;
    float x1 = p[0], x2 = p[64];
    p[0]  = x1 * cs - x2 * sn;
    p[64] = x2 * cs + x1 * sn;
}

// ============================================================================
// Causal flash attention, fp32. One CTA per (b, h, 64-query tile).
// 256 threads (tx 0..15 n-thread, ty 0..15 m-thread).
// S-tile: per-thread 4 q-rows (ty*4+i) x 4 k-rows (tx+16j).
// O accum: per-thread 4 q-rows x 8 d-cols (tx*4 and 64+tx*4).
// Online softmax; row stats reduced across 16 lanes via shfl.xor.
// ============================================================================
#define ATT_SMEM ((3*64*132 + 64*68) * 4)

__global__ __launch_bounds__(256)
void attn_kernel(const float* __restrict__ Qb, const float* __restrict__ Kb,
                 const float* __restrict__ Vb, float* __restrict__ Ob)
{
    extern __shared__ float smf[];
    float* Qs = smf;                 // [64][132]
    float* Ks = Qs + 64*132;         // [64][132]
    float* Vs = Ks + 64*132;         // [64][132]
    float* Ps = Vs + 64*132;         // [64][68]

    const int tid = threadIdx.x;
    const int tx  = tid & 15;
    const int ty  = tid >> 4;
    const int qt  = (NS/64 - 1) - blockIdx.x;   // heavy tiles launch first
    const int h   = blockIdx.y;
    const int b   = blockIdx.z;
    const int q0  = qt * 64;

    const float* qbase = Qb + (long long)b * NS * ND + h * HD;
    const float* kbase = Kb + (long long)b * NS * ND + h * HD;
    const float* vbase = Vb + (long long)b * NS * ND + h * HD;

    const float scale = 0.08838834764831845f;   // 1/sqrt(128)
    for (int e = tid; e < 64*32; e += 256) {
        int r = e >> 5, c4 = (e & 31) << 2;
        float4 v = *(const float4*)(qbase + (long long)(q0 + r) * ND + c4);
        v.x *= scale; v.y *= scale; v.z *= scale; v.w *= scale;
        *(float4*)&Qs[r*132 + c4] = v;
    }

    float m_i[4], l_i[4], o[4][8];
#pragma unroll
    for (int i = 0; i < 4; i++) {
        m_i[i] = -1e30f; l_i[i] = 0.0f;
#pragma unroll
        for (int d = 0; d < 8; d++) o[i][d] = 0.0f;
    }

    for (int jt = 0; jt <= qt; jt++) {
        const int j0 = jt * 64;
        __syncthreads();   // protect Ks/Vs/Ps from previous iteration readers
        for (int e = tid; e < 64*32; e += 256) {
            int r = e >> 5, c4 = (e & 31) << 2;
            *(float4*)&Ks[r*132 + c4] =
                *(const float4*)(kbase + (long long)(j0 + r) * ND + c4);
            *(float4*)&Vs[r*132 + c4] =
                *(const float4*)(vbase + (long long)(j0 + r) * ND + c4);
        }
        __syncthreads();

        // ---- S = Qs · Ks^T ----
        float s[4][4];
#pragma unroll
        for (int i = 0; i < 4; i++)
#pragma unroll
            for (int j = 0; j < 4; j++) s[i][j] = 0.0f;

#pragma unroll 8
        for (int kk = 0; kk < 128; kk += 4) {
            float4 a0 = *(const float4*)&Qs[(ty*4+0)*132 + kk];
            float4 a1 = *(const float4*)&Qs[(ty*4+1)*132 + kk];
            float4 a2 = *(const float4*)&Qs[(ty*4+2)*132 + kk];
            float4 a3 = *(const float4*)&Qs[(ty*4+3)*132 + kk];
            float4 b0 = *(const float4*)&Ks[(tx    )*132 + kk];
            float4 b1 = *(const float4*)&Ks[(tx+16)*132 + kk];
            float4 b2 = *(const float4*)&Ks[(tx+32)*132 + kk];
            float4 b3 = *(const float4*)&Ks[(tx+48)*132 + kk];
            float4 aa[4] = {a0, a1, a2, a3};
            float4 bb[4] = {b0, b1, b2, b3};
#pragma unroll
            for (int i = 0; i < 4; i++)
#pragma unroll
                for (int j = 0; j < 4; j++) {
                    s[i][j] += aa[i].x * bb[j].x;
                    s[i][j] += aa[i].y * bb[j].y;
                    s[i][j] += aa[i].z * bb[j].z;
                    s[i][j] += aa[i].w * bb[j].w;
                }
        }

        // ---- causal mask on the diagonal tile ----
        if (jt == qt) {
#pragma unroll
            for (int i = 0; i < 4; i++)
#pragma unroll
                for (int j = 0; j < 4; j++)
                    if (ty*4 + i < tx + 16*j) s[i][j] = -1e30f;
        }

        // ---- online softmax ----
#pragma unroll
        for (int i = 0; i < 4; i++) {
            float mx = fmaxf(fmaxf(s[i][0], s[i][1]), fmaxf(s[i][2], s[i][3]));
#pragma unroll
            for (int off = 8; off; off >>= 1)
                mx = fmaxf(mx, __shfl_xor_sync(0xffffffffu, mx, off));
            float mnew = fmaxf(m_i[i], mx);
            float corr = __expf(m_i[i] - mnew);
            float p0 = __expf(s[i][0] - mnew);
            float p1 = __expf(s[i][1] - mnew);
            float p2 = __expf(s[i][2] - mnew);
            float p3 = __expf(s[i][3] - mnew);
            float ps = p0 + p1 + p2 + p3;
#pragma unroll
            for (int off = 8; off; off >>= 1)
                ps += __shfl_xor_sync(0xffffffffu, ps, off);
            l_i[i] = l_i[i] * corr + ps;
            m_i[i] = mnew;
#pragma unroll
            for (int d = 0; d < 8; d++) o[i][d] *= corr;
            float* pr = &Ps[(ty*4+i)*68];
            pr[tx] = p0; pr[tx+16] = p1; pr[tx+32] = p2; pr[tx+48] = p3;
        }
        __syncthreads();

        // ---- O += P · V ----
#pragma unroll 4
        for (int nn = 0; nn < 64; nn += 4) {
            float pa[4][4];
            *(float4*)&pa[0][0] = *(const float4*)&Ps[(ty*4+0)*68 + nn];
            *(float4*)&pa[1][0] = *(const float4*)&Ps[(ty*4+1)*68 + nn];
            *(float4*)&pa[2][0] = *(const float4*)&Ps[(ty*4+2)*68 + nn];
            *(float4*)&pa[3][0] = *(const float4*)&Ps[(ty*4+3)*68 + nn];
#pragma unroll
            for (int jn = 0; jn < 4; jn++) {
                float4 v0 = *(const float4*)&Vs[(nn+jn)*132 +      tx*4];
                float4 v1 = *(const float4*)&Vs[(nn+jn)*132 + 64 + tx*4];
#pragma unroll
                for (int i = 0; i < 4; i++) {
                    float p = pa[i][jn];
                    o[i][0] += p * v0.x; o[i][1] += p * v0.y;
                    o[i][2] += p * v0.z; o[i][3] += p * v0.w;
                    o[i][4] += p * v1.x; o[i][5] += p * v1.y;
                    o[i][6] += p * v1.z; o[i][7] += p * v1.w;
                }
            }
        }
    }

    // ---- epilogue: O / l ----
#pragma unroll
    for (int i = 0; i < 4; i++) {
        float inv = 1.0f / l_i[i];
        float* op = Ob + (long long)(b*NS + q0 + ty*4 + i) * ND + h * HD;
        float4 r0 = make_float4(o[i][0]*inv, o[i][1]*inv, o[i][2]*inv, o[i][3]*inv);
        float4 r1 = make_float4(o[i][4]*inv, o[i][5]*inv, o[i][6]*inv, o[i][7]*inv);
        *(float4*)(op +      tx*4) = r0;
        *(float4*)(op + 64 + tx*4) = r1;
    }
}

// ============================================================================
extern "C" void kernel_launch(void* const* d_in, const int* in_sizes, int n_in,
                              void* d_out, int out_size)
{
    (void)in_sizes; (void)n_in; (void)out_size;
    const float* queries = (const float*)d_in[0];
    const float* keys    = (const float*)d_in[1];
    const float* values  = (const float*)d_in[2];
    const float* Wq = (const float*)d_in[3];
    const float* bq = (const float*)d_in[4];
    const float* Wk = (const float*)d_in[5];
    const float* bk = (const float*)d_in[6];
    const float* Wv = (const float*)d_in[7];
    const float* bv = (const float*)d_in[8];
    const float* Wo = (const float*)d_in[9];
    const float* bo = (const float*)d_in[10];
    float* out = (float*)d_out;

    float *q, *k, *v, *att;
    cudaGetSymbolAddress((void**)&q,   g_q);
    cudaGetSymbolAddress((void**)&k,   g_k);
    cudaGetSymbolAddress((void**)&v,   g_v);
    cudaGetSymbolAddress((void**)&att, g_att);

    dim3 gg(ND/256, NM/128);   // (8, 32)
    gemm_bias_kernel<<<gg, 256>>>(queries, Wq, bq, q, NM, ND, ND);
    gemm_bias_kernel<<<gg, 256>>>(keys,    Wk, bk, k, NM, ND, ND);
    gemm_bias_kernel<<<gg, 256>>>(values,  Wv, bv, v, NM, ND, ND);

    int nrope = NM * NH * 64;
    rope_kernel<<<nrope/256, 256>>>(q);
    rope_kernel<<<nrope/256, 256>>>(k);

    cudaFuncSetAttribute(attn_kernel,
                         cudaFuncAttributeMaxDynamicSharedMemorySize, ATT_SMEM);
    dim3 ga(NS/64, NH, NB);
    attn_kernel<<<ga, 256, ATT_SMEM>>>(q, k, v, att);

    gemm_bias_kernel<<<gg, 256>>>(att, Wo, bo, out, NM, ND, ND);
}

// round 3
// speedup vs baseline: 1.3679x; 1.3679x over previous
#include <cuda_runtime.h>
#include <cuda_bf16.h>
#include <cstdint>
#include <math.h>

#define NB 2
#define NS 2048
#define ND 2048
#define NH 16
#define HD 128
#define NM (NB*NS)   // 4096 rows

// ---- scratch (static device arrays; no allocation allowed) ----
__device__ float g_q[NM*ND];
__device__ float g_k[NM*ND];
__device__ float g_v[NM*ND];
__device__ float g_att[NM*ND];
__device__ __nv_bfloat16 g_wth[4ll*ND*ND];   // W^T hi, [N][K] K-major
__device__ __nv_bfloat16 g_wtl[4ll*ND*ND];   // W^T lo
__device__ __nv_bfloat16 g_ah[(long long)NM*ND];  // activation hi
__device__ __nv_bfloat16 g_al[(long long)NM*ND];  // activation lo

// ---- packed f32x2 helpers (Blackwell dual-rate fp32) ----
#define FMA2(c,a,b)   asm("fma.rn.f32x2 %0, %1, %2, %0;" : "+l"(c) : "l"(a), "l"(b))
#define MUL2(c,a)     asm("mul.rn.f32x2 %0, %0, %1;" : "+l"(c) : "l"(a))
#define PACK2(p,lo,hi) asm("mov.b64 %0, {%1, %2};" : "=l"(p) : "f"(lo), "f"(hi))
#define UNPACK2(lo,hi,p) asm("mov.b64 {%0, %1}, %2;" : "=f"(lo), "=f"(hi) : "l"(p))

__device__ __forceinline__ uint32_t smem_u32(const void* p) {
    uint32_t a;
    asm("{ .reg .u64 t; cvta.to.shared.u64 t, %1; cvt.u32.u64 %0, t; }"
        : "=r"(a) : "l"(p));
    return a;
}

// ---- base-target tensor core primitives (sm_80-class, valid on compute_103) ----
#define LDSM4(r, addr) \
    asm volatile("ldmatrix.sync.aligned.m8n8.x4.shared.b16 {%0,%1,%2,%3}, [%4];" \
        : "=r"((r)[0]), "=r"((r)[1]), "=r"((r)[2]), "=r"((r)[3]) : "r"(addr))

#define MMA16816(d, a, b) \
    asm volatile("mma.sync.aligned.m16n8k16.row.col.f32.bf16.bf16.f32 " \
        "{%0,%1,%2,%3}, {%4,%5,%6,%7}, {%8,%9}, {%0,%1,%2,%3};" \
        : "+f"((d)[0]), "+f"((d)[1]), "+f"((d)[2]), "+f"((d)[3]) \
        : "r"((a)[0]), "r"((a)[1]), "r"((a)[2]), "r"((a)[3]), \
          "r"((b)[0]), "r"((b)[1]))

#define CP_ASYNC16(dst, src) \
    asm volatile("cp.async.cg.shared.global [%0], [%1], 16;" \
                 :: "r"(dst), "l"(src) : "memory")
#define CP_COMMIT()  asm volatile("cp.async.commit_group;" ::: "memory")
#define CP_WAIT1()   asm volatile("cp.async.wait_group 1;" ::: "memory")

// ============================================================================
// Preprocessing: split fp32 into bf16 hi/lo
// ============================================================================
__global__ void split_a_kernel(const float* __restrict__ X,
                               __nv_bfloat16* __restrict__ hi,
                               __nv_bfloat16* __restrict__ lo)
{
    long long idx = (long long)(blockIdx.x * blockDim.x + threadIdx.x) * 4;
    float4 x = *(const float4*)(X + idx);
    float v[4] = {x.x, x.y, x.z, x.w};
    __nv_bfloat16 h[4], l[4];
#pragma unroll
    for (int j = 0; j < 4; j++) {
        h[j] = __float2bfloat16(v[j]);
        l[j] = __float2bfloat16(v[j] - __bfloat162float(h[j]));
    }
    *(__nv_bfloat162*)(hi + idx)     = __nv_bfloat162(h[0], h[1]);
    *(__nv_bfloat162*)(hi + idx + 2) = __nv_bfloat162(h[2], h[3]);
    *(__nv_bfloat162*)(lo + idx)     = __nv_bfloat162(l[0], l[1]);
    *(__nv_bfloat162*)(lo + idx + 2) = __nv_bfloat162(l[2], l[3]);
}

// W[K][N] fp32 -> Wt_hi/Wt_lo[N][K] bf16 (transpose + split)
__global__ void split_w_kernel(const float* __restrict__ W,
                               __nv_bfloat16* __restrict__ hi,
                               __nv_bfloat16* __restrict__ lo)
{
    __shared__ float t[32][33];
    int n0 = blockIdx.x * 32, k0 = blockIdx.y * 32;
    int tx = threadIdx.x, ty = threadIdx.y;
    for (int r = ty; r < 32; r += 8)
        t[r][tx] = W[(long long)(k0 + r) * ND + n0 + tx];
    __syncthreads();
    for (int r = ty; r < 32; r += 8) {
        float x = t[tx][r];   // = W[k0+tx][n0+r]
        __nv_bfloat16 h = __float2bfloat16(x);
        __nv_bfloat16 l = __float2bfloat16(x - __bfloat162float(h));
        long long o = (long long)(n0 + r) * ND + k0 + tx;
        hi[o] = h; lo[o] = l;
    }
}

// ============================================================================
// Split-bf16 GEMM on mma.sync (HMMA): C[M,N] = (Ah+Al)@(Bh+Bl)^T + bias
// A [M,K] row-major; B [N,K] row-major (i.e. W^T). 3 passes into fp32 accums.
// CTA 128x128, 8 warps (warp tile 64x32), K-chunk 32, cp.async double buffer.
// smem rows padded to 40 bf16 (80B) -> conflict-free ldmatrix.
// ============================================================================
#define GM_STAGE 40960                    // 4 matrices * 128 rows * 80B
#define GM_SMEM  (2*GM_STAGE)             // 81920

__global__ __launch_bounds__(256)
void gemm_mma_kernel(const __nv_bfloat16* __restrict__ Ah,
                     const __nv_bfloat16* __restrict__ Al,
                     const __nv_bfloat16* __restrict__ Bh,
                     const __nv_bfloat16* __restrict__ Bl,
                     const float* __restrict__ bias, float* __restrict__ C)
{
    extern __shared__ char dsm[];
    const uint32_t sb = smem_u32(dsm);
    const int tid  = threadIdx.x;
    const int lane = tid & 31, wid = tid >> 5;
    const int wm = wid & 1, wn = wid >> 1;      // warp tile: m 64, n 32
    const int m0 = blockIdx.y * 128, n0 = blockIdx.x * 128;

    // ---- loader mapping: 2 x 16B per matrix per chunk per thread ----
    const int lrow = tid >> 1;
    const int lc   = (tid & 1) * 16;            // first element of 32B half
    const __nv_bfloat16* gsrc[4];
    gsrc[0] = Ah + (long long)(m0 + lrow) * ND + lc;
    gsrc[1] = Al + (long long)(m0 + lrow) * ND + lc;
    gsrc[2] = Bh + (long long)(n0 + lrow) * ND + lc;
    gsrc[3] = Bl + (long long)(n0 + lrow) * ND + lc;
    const uint32_t sdst0 = sb + lrow * 80 + (tid & 1) * 32;

    float acc[4][4][4];
#pragma unroll
    for (int i = 0; i < 4; i++)
#pragma unroll
        for (int j = 0; j < 4; j++)
#pragma unroll
            for (int c = 0; c < 4; c++) acc[i][j][c] = 0.0f;

#define GM_ISSUE(ch, stage) do { \
        uint32_t s0 = sdst0 + (stage) * GM_STAGE; \
        _Pragma("unroll") \
        for (int m = 0; m < 4; m++) { \
            const __nv_bfloat16* g = gsrc[m] + (ch) * 32; \
            uint32_t d = s0 + m * 10240; \
            CP_ASYNC16(d, g); \
            CP_ASYNC16(d + 16, g + 8); \
        } \
        CP_COMMIT(); \
    } while (0)

    GM_ISSUE(0, 0);
    GM_ISSUE(1, 1);

    for (int ch = 0; ch < 64; ch++) {
        const int st = ch & 1;
        CP_WAIT1();
        __syncthreads();
        const uint32_t abase = sb + st * GM_STAGE + (wm * 64) * 80;
        const uint32_t bbase = sb + st * GM_STAGE + 20480 + (wn * 32) * 80;
        const uint32_t lrow16 = (lane & 15) * 80;
        const uint32_t lcol8  = (lane >> 4) * 16;   // bytes: 8 bf16
#pragma unroll
        for (int kk = 0; kk < 32; kk += 16) {
            uint32_t ah[4][4], al[4][4], bh[4][2], bl[4][2];
#pragma unroll
            for (int mt = 0; mt < 4; mt++) {
                uint32_t addr = abase + mt * 16 * 80 + lrow16 + kk * 2 + lcol8;
                LDSM4(ah[mt], addr);
                LDSM4(al[mt], addr + 10240);
            }
#pragma unroll
            for (int np = 0; np < 2; np++) {
                uint32_t addr = bbase + np * 16 * 80 + lrow16 + kk * 2 + lcol8;
                uint32_t r[4], s[4];
                LDSM4(r, addr);
                LDSM4(s, addr + 10240);
                bh[np*2+0][0] = r[0]; bh[np*2+0][1] = r[2];
                bh[np*2+1][0] = r[1]; bh[np*2+1][1] = r[3];
                bl[np*2+0][0] = s[0]; bl[np*2+0][1] = s[2];
                bl[np*2+1][0] = s[1]; bl[np*2+1][1] = s[3];
            }
#pragma unroll
            for (int mt = 0; mt < 4; mt++)
#pragma unroll
                for (int nt = 0; nt < 4; nt++) {
                    MMA16816(acc[mt][nt], ah[mt], bh[nt]);
                    MMA16816(acc[mt][nt], ah[mt], bl[nt]);
                    MMA16816(acc[mt][nt], al[mt], bh[nt]);
                }
        }
        __syncthreads();
        if (ch + 2 < 64) GM_ISSUE(ch + 2, st);
    }

    // ---- epilogue: accums + bias -> C ----
    const int r0 = m0 + wm * 64 + (lane >> 2);
    const int c0 = n0 + wn * 32 + (lane & 3) * 2;
#pragma unroll
    for (int nt = 0; nt < 4; nt++) {
        const int c = c0 + nt * 8;
        const float b0 = bias[c], b1 = bias[c + 1];
#pragma unroll
        for (int mt = 0; mt < 4; mt++) {
            const int r = r0 + mt * 16;
            float2 v0 = make_float2(acc[mt][nt][0] + b0, acc[mt][nt][1] + b1);
            float2 v1 = make_float2(acc[mt][nt][2] + b0, acc[mt][nt][3] + b1);
            *(float2*)&C[(long long)r * ND + c]       = v0;
            *(float2*)&C[(long long)(r + 8) * ND + c] = v1;
        }
    }
#undef GM_ISSUE
}

// ============================================================================
// RoPE in place on [NM, ND] buffer: per head of 128 dims, pairs (i, i+64).
// ============================================================================
__global__ void rope_kernel(float* __restrict__ X)
{
    int idx = blockIdx.x * blockDim.x + threadIdx.x;  // NM * NH * 64
    int i   = idx & 63;
    int h   = (idx >> 6) & (NH - 1);
    int row = idx >> 10;
    int s   = row & (NS - 1);
    float inv = powf(10000.0f, -(float)i / 64.0f);
    float ang = (float)s * inv;
    float sn, cs;
    sincosf(ang, &sn, &cs);
    float* p = X + (long long)row * ND + h * HD + i;
    float x1 = p[0], x2 = p[64];
    p[0]  = x1 * cs - x2 * sn;
    p[64] = x2 * cs + x1 * sn;
}

// ============================================================================
// Causal flash attention, fp32 with packed f32x2 FMAs in QK^T and PV.
// One CTA per (b, h, 64-query tile); 256 threads.
// ============================================================================
#define ATT_SMEM ((3*64*132 + 64*68) * 4)

__global__ __launch_bounds__(256)
void attn_kernel(const float* __restrict__ Qb, const float* __restrict__ Kb,
                 const float* __restrict__ Vb, float* __restrict__ Ob)
{
    extern __shared__ float smf[];
    float* Qs = smf;                 // [64][132]
    float* Ks = Qs + 64*132;         // [64][132]
    float* Vs = Ks + 64*132;         // [64][132]
    float* Ps = Vs + 64*132;         // [64][68]

    const int tid = threadIdx.x;
    const int tx  = tid & 15;
    const int ty  = tid >> 4;
    const int qt  = (NS/64 - 1) - blockIdx.x;   // heavy tiles launch first
    const int h   = blockIdx.y;
    const int b   = blockIdx.z;
    const int q0  = qt * 64;

    const float* qbase = Qb + (long long)b * NS * ND + h * HD;
    const float* kbase = Kb + (long long)b * NS * ND + h * HD;
    const float* vbase = Vb + (long long)b * NS * ND + h * HD;

    const float scale = 0.08838834764831845f;   // 1/sqrt(128)
    for (int e = tid; e < 64*32; e += 256) {
        int r = e >> 5, c4 = (e & 31) << 2;
        float4 v = *(const float4*)(qbase + (long long)(q0 + r) * ND + c4);
        v.x *= scale; v.y *= scale; v.z *= scale; v.w *= scale;
        *(float4*)&Qs[r*132 + c4] = v;
    }

    float m_i[4], l_i[4];
    unsigned long long o2[4][4];
#pragma unroll
    for (int i = 0; i < 4; i++) {
        m_i[i] = -1e30f; l_i[i] = 0.0f;
#pragma unroll
        for (int d = 0; d < 4; d++) o2[i][d] = 0ULL;
    }

    for (int jt = 0; jt <= qt; jt++) {
        const int j0 = jt * 64;
        __syncthreads();   // protect Ks/Vs/Ps from previous iteration readers
        for (int e = tid; e < 64*32; e += 256) {
            int r = e >> 5, c4 = (e & 31) << 2;
            *(float4*)&Ks[r*132 + c4] =
                *(const float4*)(kbase + (long long)(j0 + r) * ND + c4);
            *(float4*)&Vs[r*132 + c4] =
                *(const float4*)(vbase + (long long)(j0 + r) * ND + c4);
        }
        __syncthreads();

        // ---- S = Qs · Ks^T (packed f32x2 over k-pairs) ----
        unsigned long long s2[4][4];
#pragma unroll
        for (int i = 0; i < 4; i++)
#pragma unroll
            for (int j = 0; j < 4; j++) s2[i][j] = 0ULL;

#pragma unroll 8
        for (int kk = 0; kk < 128; kk += 4) {
            ulonglong2 a[4], bb[4];
            a[0] = *(const ulonglong2*)&Qs[(ty*4+0)*132 + kk];
            a[1] = *(const ulonglong2*)&Qs[(ty*4+1)*132 + kk];
            a[2] = *(const ulonglong2*)&Qs[(ty*4+2)*132 + kk];
            a[3] = *(const ulonglong2*)&Qs[(ty*4+3)*132 + kk];
            bb[0] = *(const ulonglong2*)&Ks[(tx    )*132 + kk];
            bb[1] = *(const ulonglong2*)&Ks[(tx+16)*132 + kk];
            bb[2] = *(const ulonglong2*)&Ks[(tx+32)*132 + kk];
            bb[3] = *(const ulonglong2*)&Ks[(tx+48)*132 + kk];
#pragma unroll
            for (int i = 0; i < 4; i++)
#pragma unroll
                for (int j = 0; j < 4; j++) {
                    FMA2(s2[i][j], a[i].x, bb[j].x);
                    FMA2(s2[i][j], a[i].y, bb[j].y);
                }
        }
        float s[4][4];
#pragma unroll
        for (int i = 0; i < 4; i++)
#pragma unroll
            for (int j = 0; j < 4; j++) {
                float lo, hi;
                UNPACK2(lo, hi, s2[i][j]);
                s[i][j] = lo + hi;
            }

        // ---- causal mask on the diagonal tile ----
        if (jt == qt) {
#pragma unroll
            for (int i = 0; i < 4; i++)
#pragma unroll
                for (int j = 0; j < 4; j++)
                    if (ty*4 + i < tx + 16*j) s[i][j] = -1e30f;
        }

        // ---- online softmax ----
#pragma unroll
        for (int i = 0; i < 4; i++) {
            float mx = fmaxf(fmaxf(s[i][0], s[i][1]), fmaxf(s[i][2], s[i][3]));
#pragma unroll
            for (int off = 8; off; off >>= 1)
                mx = fmaxf(mx, __shfl_xor_sync(0xffffffffu, mx, off));
            float mnew = fmaxf(m_i[i], mx);
            float corr = __expf(m_i[i] - mnew);
            float p0 = __expf(s[i][0] - mnew);
            float p1 = __expf(s[i][1] - mnew);
            float p2 = __expf(s[i][2] - mnew);
            float p3 = __expf(s[i][3] - mnew);
            float ps = p0 + p1 + p2 + p3;
#pragma unroll
            for (int off = 8; off; off >>= 1)
                ps += __shfl_xor_sync(0xffffffffu, ps, off);
            l_i[i] = l_i[i] * corr + ps;
            m_i[i] = mnew;
            unsigned long long cp;
            PACK2(cp, corr, corr);
            MUL2(o2[i][0], cp); MUL2(o2[i][1], cp);
            MUL2(o2[i][2], cp); MUL2(o2[i][3], cp);
            float* pr = &Ps[(ty*4+i)*68];
            pr[tx] = p0; pr[tx+16] = p1; pr[tx+32] = p2; pr[tx+48] = p3;
        }
        __syncthreads();

        // ---- O += P · V (packed f32x2 over d-pairs) ----
#pragma unroll 4
        for (int nn = 0; nn < 64; nn += 4) {
            float pa[4][4];
            *(float4*)&pa[0][0] = *(const float4*)&Ps[(ty*4+0)*68 + nn];
            *(float4*)&pa[1][0] = *(const float4*)&Ps[(ty*4+1)*68 + nn];
            *(float4*)&pa[2][0] = *(const float4*)&Ps[(ty*4+2)*68 + nn];
            *(float4*)&pa[3][0] = *(const float4*)&Ps[(ty*4+3)*68 + nn];
#pragma unroll
            for (int jn = 0; jn < 4; jn++) {
                ulonglong2 v0 = *(const ulonglong2*)&Vs[(nn+jn)*132 +      tx*4];
                ulonglong2 v1 = *(const ulonglong2*)&Vs[(nn+jn)*132 + 64 + tx*4];
#pragma unroll
                for (int i = 0; i < 4; i++) {
                    unsigned long long pp;
                    PACK2(pp, pa[i][jn], pa[i][jn]);
                    FMA2(o2[i][0], pp, v0.x);
                    FMA2(o2[i][1], pp, v0.y);
                    FMA2(o2[i][2], pp, v1.x);
                    FMA2(o2[i][3], pp, v1.y);
                }
            }
        }
    }

    // ---- epilogue: O / l ----
#pragma unroll
    for (int i = 0; i < 4; i++) {
        float inv = 1.0f / l_i[i];
        float* op = Ob + (long long)(b*NS + q0 + ty*4 + i) * ND + h * HD;
        float x0,x1,x2,x3,x4,x5,x6,x7;
        UNPACK2(x0, x1, o2[i][0]);
        UNPACK2(x2, x3, o2[i][1]);
        UNPACK2(x4, x5, o2[i][2]);
        UNPACK2(x6, x7, o2[i][3]);
        float4 r0 = make_float4(x0*inv, x1*inv, x2*inv, x3*inv);
        float4 r1 = make_float4(x4*inv, x5*inv, x6*inv, x7*inv);
        *(float4*)(op +      tx*4) = r0;
        *(float4*)(op + 64 + tx*4) = r1;
    }
}

// ============================================================================
extern "C" void kernel_launch(void* const* d_in, const int* in_sizes, int n_in,
                              void* d_out, int out_size)
{
    (void)in_sizes; (void)n_in; (void)out_size;
    const float* queries = (const float*)d_in[0];
    const float* keys    = (const float*)d_in[1];
    const float* values  = (const float*)d_in[2];
    const float* Wq = (const float*)d_in[3];
    const float* bq = (const float*)d_in[4];
    const float* Wk = (const float*)d_in[5];
    const float* bk = (const float*)d_in[6];
    const float* Wv = (const float*)d_in[7];
    const float* bv = (const float*)d_in[8];
    const float* Wo = (const float*)d_in[9];
    const float* bo = (const float*)d_in[10];
    float* out = (float*)d_out;

    float *q, *k, *v, *att;
    __nv_bfloat16 *wth, *wtl, *ah, *al;
    cudaGetSymbolAddress((void**)&q,   g_q);
    cudaGetSymbolAddress((void**)&k,   g_k);
    cudaGetSymbolAddress((void**)&v,   g_v);
    cudaGetSymbolAddress((void**)&att, g_att);
    cudaGetSymbolAddress((void**)&wth, g_wth);
    cudaGetSymbolAddress((void**)&wtl, g_wtl);
    cudaGetSymbolAddress((void**)&ah,  g_ah);
    cudaGetSymbolAddress((void**)&al,  g_al);

    cudaFuncSetAttribute(gemm_mma_kernel,
                         cudaFuncAttributeMaxDynamicSharedMemorySize, GM_SMEM);
    cudaFuncSetAttribute(attn_kernel,
                         cudaFuncAttributeMaxDynamicSharedMemorySize, ATT_SMEM);

    // ---- split + transpose weights ----
    const float* Ws[4] = {Wq, Wk, Wv, Wo};
    dim3 gw(ND/32, ND/32), bw(32, 8);
    for (int i = 0; i < 4; i++)
        split_w_kernel<<<gw, bw>>>(Ws[i], wth + (long long)i*ND*ND,
                                          wtl + (long long)i*ND*ND);

    const int nsplit = NM*ND/4/256;
    dim3 gtg(ND/128, NM/128);                  // (16, 32)

    // ---- projections on tensor cores ----
    split_a_kernel<<<nsplit, 256>>>(queries, ah, al);
    gemm_mma_kernel<<<gtg, 256, GM_SMEM>>>(ah, al, wth + 0ll*ND*ND, wtl + 0ll*ND*ND, bq, q);
    split_a_kernel<<<nsplit, 256>>>(keys, ah, al);
    gemm_mma_kernel<<<gtg, 256, GM_SMEM>>>(ah, al, wth + 1ll*ND*ND, wtl + 1ll*ND*ND, bk, k);
    split_a_kernel<<<nsplit, 256>>>(values, ah, al);
    gemm_mma_kernel<<<gtg, 256, GM_SMEM>>>(ah, al, wth + 2ll*ND*ND, wtl + 2ll*ND*ND, bv, v);

    // ---- RoPE ----
    int nrope = NM * NH * 64;
    rope_kernel<<<nrope/256, 256>>>(q);
    rope_kernel<<<nrope/256, 256>>>(k);

    // ---- attention ----
    dim3 ga(NS/64, NH, NB);
    attn_kernel<<<ga, 256, ATT_SMEM>>>(q, k, v, att);

    // ---- output projection ----
    split_a_kernel<<<nsplit, 256>>>(att, ah, al);
    gemm_mma_kernel<<<gtg, 256, GM_SMEM>>>(ah, al, wth + 3ll*ND*ND, wtl + 3ll*ND*ND, bo, out);
}

// round 4
// speedup vs baseline: 1.7077x; 1.2484x over previous
#include <cuda_runtime.h>
#include <cuda_bf16.h>
#include <cstdint>
#include <math.h>

#define NB 2
#define NS 2048
#define ND 2048
#define NH 16
#define HD 128
#define NM (NB*NS)   // 4096 rows

// ---- scratch (static device arrays; no allocation allowed) ----
__device__ float g_q[NM*ND];                     // fp32 Q proj (pre-rope)
__device__ float g_k[NM*ND];                     // fp32 K proj (pre-rope)
__device__ __nv_bfloat16 g_wth[4ll*ND*ND];       // W^T hi, [N][K] K-major
__device__ __nv_bfloat16 g_wtl[4ll*ND*ND];       // W^T lo
__device__ __nv_bfloat16 g_ah[(long long)NM*ND]; // activation hi (gemm A / att out)
__device__ __nv_bfloat16 g_al[(long long)NM*ND]; // activation lo
__device__ __nv_bfloat16 g_qh[(long long)NM*ND]; // roped Q hi (scaled)
__device__ __nv_bfloat16 g_ql[(long long)NM*ND];
__device__ __nv_bfloat16 g_kh[(long long)NM*ND]; // roped K hi
__device__ __nv_bfloat16 g_kl[(long long)NM*ND];
__device__ __nv_bfloat16 g_vh[(long long)NM*ND]; // V proj hi
__device__ __nv_bfloat16 g_vl[(long long)NM*ND];

__device__ __forceinline__ uint32_t smem_u32(const void* p) {
    uint32_t a;
    asm("{ .reg .u64 t; cvta.to.shared.u64 t, %1; cvt.u32.u64 %0, t; }"
        : "=r"(a) : "l"(p));
    return a;
}

// ---- base-target tensor core primitives (sm_80-class, valid on compute_103) ----
#define LDSM4(r, addr) \
    asm volatile("ldmatrix.sync.aligned.m8n8.x4.shared.b16 {%0,%1,%2,%3}, [%4];" \
        : "=r"((r)[0]), "=r"((r)[1]), "=r"((r)[2]), "=r"((r)[3]) : "r"(addr))

#define LDSM4T(r, addr) \
    asm volatile("ldmatrix.sync.aligned.m8n8.x4.trans.shared.b16 {%0,%1,%2,%3}, [%4];" \
        : "=r"((r)[0]), "=r"((r)[1]), "=r"((r)[2]), "=r"((r)[3]) : "r"(addr))

#define MMA16816(d, a, b) \
    asm volatile("mma.sync.aligned.m16n8k16.row.col.f32.bf16.bf16.f32 " \
        "{%0,%1,%2,%3}, {%4,%5,%6,%7}, {%8,%9}, {%0,%1,%2,%3};" \
        : "+f"((d)[0]), "+f"((d)[1]), "+f"((d)[2]), "+f"((d)[3]) \
        : "r"((a)[0]), "r"((a)[1]), "r"((a)[2]), "r"((a)[3]), \
          "r"((b)[0]), "r"((b)[1]))

#define CP_ASYNC16(dst, src) \
    asm volatile("cp.async.cg.shared.global [%0], [%1], 16;" \
                 :: "r"(dst), "l"(src) : "memory")
#define CP_COMMIT()  asm volatile("cp.async.commit_group;" ::: "memory")
#define CP_WAIT1()   asm volatile("cp.async.wait_group 1;" ::: "memory")
#define CP_WAIT0()   asm volatile("cp.async.wait_group 0;" ::: "memory")

// pack two f32 into bf16x2 (x -> low half)
__device__ __forceinline__ uint32_t bf16x2_pack(float lo, float hi) {
    __nv_bfloat162 v = __floats2bfloat162_rn(lo, hi);
    return *reinterpret_cast<uint32_t*>(&v);
}

// ============================================================================
// Preprocessing: split fp32 into bf16 hi/lo
// ============================================================================
__global__ void split_a_kernel(const float* __restrict__ X,
                               __nv_bfloat16* __restrict__ hi,
                               __nv_bfloat16* __restrict__ lo)
{
    long long idx = (long long)(blockIdx.x * blockDim.x + threadIdx.x) * 4;
    float4 x = *(const float4*)(X + idx);
    float v[4] = {x.x, x.y, x.z, x.w};
    __nv_bfloat16 h[4], l[4];
#pragma unroll
    for (int j = 0; j < 4; j++) {
        h[j] = __float2bfloat16(v[j]);
        l[j] = __float2bfloat16(v[j] - __bfloat162float(h[j]));
    }
    *(__nv_bfloat162*)(hi + idx)     = __nv_bfloat162(h[0], h[1]);
    *(__nv_bfloat162*)(hi + idx + 2) = __nv_bfloat162(h[2], h[3]);
    *(__nv_bfloat162*)(lo + idx)     = __nv_bfloat162(l[0], l[1]);
    *(__nv_bfloat162*)(lo + idx + 2) = __nv_bfloat162(l[2], l[3]);
}

// W[K][N] fp32 -> Wt_hi/Wt_lo[N][K] bf16 (transpose + split)
__global__ void split_w_kernel(const float* __restrict__ W,
                               __nv_bfloat16* __restrict__ hi,
                               __nv_bfloat16* __restrict__ lo)
{
    __shared__ float t[32][33];
    int n0 = blockIdx.x * 32, k0 = blockIdx.y * 32;
    int tx = threadIdx.x, ty = threadIdx.y;
    for (int r = ty; r < 32; r += 8)
        t[r][tx] = W[(long long)(k0 + r) * ND + n0 + tx];
    __syncthreads();
    for (int r = ty; r < 32; r += 8) {
        float x = t[tx][r];   // = W[k0+tx][n0+r]
        __nv_bfloat16 h = __float2bfloat16(x);
        __nv_bfloat16 l = __float2bfloat16(x - __bfloat162float(h));
        long long o = (long long)(n0 + r) * ND + k0 + tx;
        hi[o] = h; lo[o] = l;
    }
}

// ============================================================================
// Split-bf16 GEMM on mma.sync: C = (Ah+Al)@(Bh+Bl)^T + bias
// Outputs: fp32 C (if non-null) and/or bf16 hi/lo (if non-null).
// ============================================================================
#define GM_STAGE 40960                    // 4 matrices * 128 rows * 80B
#define GM_SMEM  (2*GM_STAGE)             // 81920

__global__ __launch_bounds__(256)
void gemm_mma_kernel(const __nv_bfloat16* __restrict__ Ah,
                     const __nv_bfloat16* __restrict__ Al,
                     const __nv_bfloat16* __restrict__ Bh,
                     const __nv_bfloat16* __restrict__ Bl,
                     const float* __restrict__ bias,
                     float* __restrict__ C,
                     __nv_bfloat16* __restrict__ Chi,
                     __nv_bfloat16* __restrict__ Clo)
{
    extern __shared__ char dsm[];
    const uint32_t sb = smem_u32(dsm);
    const int tid  = threadIdx.x;
    const int lane = tid & 31, wid = tid >> 5;
    const int wm = wid & 1, wn = wid >> 1;      // warp tile: m 64, n 32
    const int m0 = blockIdx.y * 128, n0 = blockIdx.x * 128;

    const int lrow = tid >> 1;
    const int lc   = (tid & 1) * 16;
    const __nv_bfloat16* gsrc[4];
    gsrc[0] = Ah + (long long)(m0 + lrow) * ND + lc;
    gsrc[1] = Al + (long long)(m0 + lrow) * ND + lc;
    gsrc[2] = Bh + (long long)(n0 + lrow) * ND + lc;
    gsrc[3] = Bl + (long long)(n0 + lrow) * ND + lc;
    const uint32_t sdst0 = sb + lrow * 80 + (tid & 1) * 32;

    float acc[4][4][4];
#pragma unroll
    for (int i = 0; i < 4; i++)
#pragma unroll
        for (int j = 0; j < 4; j++)
#pragma unroll
            for (int c = 0; c < 4; c++) acc[i][j][c] = 0.0f;

#define GM_ISSUE(ch, stage) do { \
        uint32_t s0 = sdst0 + (stage) * GM_STAGE; \
        _Pragma("unroll") \
        for (int m = 0; m < 4; m++) { \
            const __nv_bfloat16* g = gsrc[m] + (ch) * 32; \
            uint32_t d = s0 + m * 10240; \
            CP_ASYNC16(d, g); \
            CP_ASYNC16(d + 16, g + 8); \
        } \
        CP_COMMIT(); \
    } while (0)

    GM_ISSUE(0, 0);
    GM_ISSUE(1, 1);

    for (int ch = 0; ch < 64; ch++) {
        const int st = ch & 1;
        CP_WAIT1();
        __syncthreads();
        const uint32_t abase = sb + st * GM_STAGE + (wm * 64) * 80;
        const uint32_t bbase = sb + st * GM_STAGE + 20480 + (wn * 32) * 80;
        const uint32_t lrow16 = (lane & 15) * 80;
        const uint32_t lcol8  = (lane >> 4) * 16;
#pragma unroll
        for (int kk = 0; kk < 32; kk += 16) {
            uint32_t ah[4][4], al[4][4], bh[4][2], bl[4][2];
#pragma unroll
            for (int mt = 0; mt < 4; mt++) {
                uint32_t addr = abase + mt * 16 * 80 + lrow16 + kk * 2 + lcol8;
                LDSM4(ah[mt], addr);
                LDSM4(al[mt], addr + 10240);
            }
#pragma unroll
            for (int np = 0; np < 2; np++) {
                uint32_t addr = bbase + np * 16 * 80 + lrow16 + kk * 2 + lcol8;
                uint32_t r[4], s[4];
                LDSM4(r, addr);
                LDSM4(s, addr + 10240);
                bh[np*2+0][0] = r[0]; bh[np*2+0][1] = r[2];
                bh[np*2+1][0] = r[1]; bh[np*2+1][1] = r[3];
                bl[np*2+0][0] = s[0]; bl[np*2+0][1] = s[2];
                bl[np*2+1][0] = s[1]; bl[np*2+1][1] = s[3];
            }
#pragma unroll
            for (int mt = 0; mt < 4; mt++)
#pragma unroll
                for (int nt = 0; nt < 4; nt++) {
                    MMA16816(acc[mt][nt], ah[mt], bh[nt]);
                    MMA16816(acc[mt][nt], ah[mt], bl[nt]);
                    MMA16816(acc[mt][nt], al[mt], bh[nt]);
                }
        }
        __syncthreads();
        if (ch + 2 < 64) GM_ISSUE(ch + 2, st);
        else CP_COMMIT();          // keep group-count invariant for WAIT1
    }

    // ---- epilogue ----
    const int r0 = m0 + wm * 64 + (lane >> 2);
    const int c0 = n0 + wn * 32 + (lane & 3) * 2;
#pragma unroll
    for (int nt = 0; nt < 4; nt++) {
        const int c = c0 + nt * 8;
        const float b0 = bias[c], b1 = bias[c + 1];
#pragma unroll
        for (int mt = 0; mt < 4; mt++) {
            const int r = r0 + mt * 16;
            float v00 = acc[mt][nt][0] + b0, v01 = acc[mt][nt][1] + b1;
            float v10 = acc[mt][nt][2] + b0, v11 = acc[mt][nt][3] + b1;
            if (C) {
                *(float2*)&C[(long long)r * ND + c]       = make_float2(v00, v01);
                *(float2*)&C[(long long)(r + 8) * ND + c] = make_float2(v10, v11);
            }
            if (Chi) {
                uint32_t h0 = bf16x2_pack(v00, v01);
                uint32_t h1 = bf16x2_pack(v10, v11);
                float h00 = __uint_as_float(h0 << 16), h01 = __uint_as_float(h0 & 0xFFFF0000u);
                float h10 = __uint_as_float(h1 << 16), h11 = __uint_as_float(h1 & 0xFFFF0000u);
                uint32_t l0 = bf16x2_pack(v00 - h00, v01 - h01);
                uint32_t l1 = bf16x2_pack(v10 - h10, v11 - h11);
                *(uint32_t*)&Chi[(long long)r * ND + c]       = h0;
                *(uint32_t*)&Chi[(long long)(r + 8) * ND + c] = h1;
                *(uint32_t*)&Clo[(long long)r * ND + c]       = l0;
                *(uint32_t*)&Clo[(long long)(r + 8) * ND + c] = l1;
            }
        }
    }
#undef GM_ISSUE
}

// ============================================================================
// RoPE + split: read fp32 proj, rotate, scale, write bf16 hi/lo
// ============================================================================
__global__ void rope_split_kernel(const float* __restrict__ X,
                                  __nv_bfloat16* __restrict__ hi,
                                  __nv_bfloat16* __restrict__ lo,
                                  float scale)
{
    int idx = blockIdx.x * blockDim.x + threadIdx.x;  // NM * NH * 64
    int i   = idx & 63;
    int h   = (idx >> 6) & (NH - 1);
    int row = idx >> 10;
    int s   = row & (NS - 1);
    float invf = powf(10000.0f, -(float)i / 64.0f);
    float ang = (float)s * invf;
    float sn, cs;
    sincosf(ang, &sn, &cs);
    long long off = (long long)row * ND + h * HD + i;
    float x1 = X[off], x2 = X[off + 64];
    float o1 = (x1 * cs - x2 * sn) * scale;
    float o2 = (x2 * cs + x1 * sn) * scale;
    __nv_bfloat16 h1 = __float2bfloat16(o1);
    __nv_bfloat16 h2 = __float2bfloat16(o2);
    hi[off]      = h1;
    hi[off + 64] = h2;
    lo[off]      = __float2bfloat16(o1 - __bfloat162float(h1));
    lo[off + 64] = __float2bfloat16(o2 - __bfloat162float(h2));
}

// ============================================================================
// Causal flash attention on mma.sync, split-bf16 3-pass both GEMMs.
// CTA: (b, h, 128-q tile); 8 warps, each owns 16 q rows.
// K/V tiles of 64 keys, cp.async double-buffered.
// Output written directly as bf16 hi/lo (feeds the final projection GEMM).
// ============================================================================
#define AT_RS    272                       // row stride bytes (136 bf16)
#define AT_TSIZE (64*AT_RS)                // 17408 per matrix tile
#define AT_STAGE (4*AT_TSIZE)              // 69632: Kh,Kl,Vh,Vl
#define AT_SMEM  (2*AT_STAGE)              // 139264

__global__ __launch_bounds__(256)
void attn_mma_kernel(const __nv_bfloat16* __restrict__ qh,
                     const __nv_bfloat16* __restrict__ ql,
                     const __nv_bfloat16* __restrict__ kh,
                     const __nv_bfloat16* __restrict__ kl,
                     const __nv_bfloat16* __restrict__ vh,
                     const __nv_bfloat16* __restrict__ vl,
                     __nv_bfloat16* __restrict__ oh,
                     __nv_bfloat16* __restrict__ ol)
{
    extern __shared__ char dsm[];
    const uint32_t sb = smem_u32(dsm);
    const int tid  = threadIdx.x;
    const int lane = tid & 31, w = tid >> 5;
    const int qt = (NS/128 - 1) - blockIdx.x;   // heavy tiles first
    const int h  = blockIdx.y;
    const int b  = blockIdx.z;
    const int q0 = qt * 128;
    const long long gbase = (long long)b * NS * ND + h * HD;

    // ---- stage Q (hi then lo) into stage-0 region, 256B payload/row ----
    {
        int r = tid & 127;
        const __nv_bfloat16* src = ((tid < 128) ? qh : ql) + gbase + (long long)(q0 + r) * ND;
        uint32_t dst = sb + ((tid < 128) ? 0 : 128*AT_RS) + r * AT_RS;
#pragma unroll
        for (int c = 0; c < 16; c++) CP_ASYNC16(dst + c*16, src + c*8);
        CP_COMMIT();
        CP_WAIT0();
        __syncthreads();
    }

    // ---- Q fragments to registers (8 k16-chunks, hi+lo) ----
    uint32_t qfh[8][4], qfl[8][4];
    {
        uint32_t qaddr = sb + (w*16 + (lane & 15)) * AT_RS + (lane >> 4) * 16;
#pragma unroll
        for (int kc = 0; kc < 8; kc++) {
            LDSM4(qfh[kc], qaddr + kc*32);
            LDSM4(qfl[kc], qaddr + kc*32 + 128*AT_RS);
        }
    }
    __syncthreads();   // done reading stage-0 region

    // ---- K/V tile loader: 4 matrices x 64 rows, one row per thread ----
    const __nv_bfloat16* kvsrc;
    {
        const __nv_bfloat16* s4[4] = {kh, kl, vh, vl};
        kvsrc = s4[tid >> 6] + gbase + (long long)(tid & 63) * ND;
    }
    const uint32_t kvdst = sb + (tid >> 6) * AT_TSIZE + (tid & 63) * AT_RS;

#define AT_ISSUE(jt, st) do { \
        const __nv_bfloat16* g = kvsrc + (long long)(jt) * 64 * ND; \
        uint32_t d = kvdst + (st) * AT_STAGE; \
        _Pragma("unroll") \
        for (int c = 0; c < 16; c++) CP_ASYNC16(d + c*16, g + c*8); \
        CP_COMMIT(); \
    } while (0)

    const int njt = 2*qt + 2;
    AT_ISSUE(0, 0);
    AT_ISSUE(1, 1);

    float m0v = -1e30f, m1v = -1e30f, l0 = 0.0f, l1 = 0.0f;
    float od[16][4];
#pragma unroll
    for (int nd = 0; nd < 16; nd++)
#pragma unroll
        for (int c = 0; c < 4; c++) od[nd][c] = 0.0f;

    for (int jt = 0; jt < njt; jt++) {
        const int st = jt & 1;
        CP_WAIT1();
        __syncthreads();
        const uint32_t kbase = sb + st * AT_STAGE;
        const uint32_t vbase = kbase + 2 * AT_TSIZE;

        // ---- S = Q·K^T (16 x 64 per warp), 3 passes ----
        float sc[8][4];
#pragma unroll
        for (int n = 0; n < 8; n++)
#pragma unroll
            for (int c = 0; c < 4; c++) sc[n][c] = 0.0f;

#pragma unroll
        for (int kc = 0; kc < 8; kc++) {
#pragma unroll
            for (int ng = 0; ng < 4; ng++) {
                uint32_t addr = kbase + (ng*16 + (lane & 15)) * AT_RS
                              + kc*32 + (lane >> 4) * 16;
                uint32_t rh[4], rl[4];
                LDSM4(rh, addr);
                LDSM4(rl, addr + AT_TSIZE);
                uint32_t b0h[2] = {rh[0], rh[2]}, b1h[2] = {rh[1], rh[3]};
                uint32_t b0l[2] = {rl[0], rl[2]}, b1l[2] = {rl[1], rl[3]};
                MMA16816(sc[2*ng],   qfh[kc], b0h);
                MMA16816(sc[2*ng],   qfh[kc], b0l);
                MMA16816(sc[2*ng],   qfl[kc], b0h);
                MMA16816(sc[2*ng+1], qfh[kc], b1h);
                MMA16816(sc[2*ng+1], qfh[kc], b1l);
                MMA16816(sc[2*ng+1], qfl[kc], b1h);
            }
        }

        // ---- causal mask (only the two diagonal k-tiles) ----
        if (jt >= njt - 2) {
            const int qrow = q0 + w*16 + (lane >> 2);
            const int kc0  = jt*64 + (lane & 3)*2;
#pragma unroll
            for (int n = 0; n < 8; n++) {
                int kcol = kc0 + n*8;
                if (kcol     > qrow)     sc[n][0] = -1e30f;
                if (kcol + 1 > qrow)     sc[n][1] = -1e30f;
                if (kcol     > qrow + 8) sc[n][2] = -1e30f;
                if (kcol + 1 > qrow + 8) sc[n][3] = -1e30f;
            }
        }

        // ---- online softmax ----
        float mx0 = -1e30f, mx1 = -1e30f;
#pragma unroll
        for (int n = 0; n < 8; n++) {
            mx0 = fmaxf(mx0, fmaxf(sc[n][0], sc[n][1]));
            mx1 = fmaxf(mx1, fmaxf(sc[n][2], sc[n][3]));
        }
        mx0 = fmaxf(mx0, __shfl_xor_sync(0xffffffffu, mx0, 1));
        mx0 = fmaxf(mx0, __shfl_xor_sync(0xffffffffu, mx0, 2));
        mx1 = fmaxf(mx1, __shfl_xor_sync(0xffffffffu, mx1, 1));
        mx1 = fmaxf(mx1, __shfl_xor_sync(0xffffffffu, mx1, 2));
        float mn0 = fmaxf(m0v, mx0), mn1 = fmaxf(m1v, mx1);
        float corr0 = __expf(m0v - mn0), corr1 = __expf(m1v - mn1);
        float ps0 = 0.0f, ps1 = 0.0f;
#pragma unroll
        for (int n = 0; n < 8; n++) {
            sc[n][0] = __expf(sc[n][0] - mn0);
            sc[n][1] = __expf(sc[n][1] - mn0);
            sc[n][2] = __expf(sc[n][2] - mn1);
            sc[n][3] = __expf(sc[n][3] - mn1);
            ps0 += sc[n][0] + sc[n][1];
            ps1 += sc[n][2] + sc[n][3];
        }
        ps0 += __shfl_xor_sync(0xffffffffu, ps0, 1);
        ps0 += __shfl_xor_sync(0xffffffffu, ps0, 2);
        ps1 += __shfl_xor_sync(0xffffffffu, ps1, 1);
        ps1 += __shfl_xor_sync(0xffffffffu, ps1, 2);
        l0 = l0 * corr0 + ps0;  m0v = mn0;
        l1 = l1 * corr1 + ps1;  m1v = mn1;
#pragma unroll
        for (int nd = 0; nd < 16; nd++) {
            od[nd][0] *= corr0; od[nd][1] *= corr0;
            od[nd][2] *= corr1; od[nd][3] *= corr1;
        }

        // ---- repack P (C-frags) into A-frags, bf16 hi/lo ----
        uint32_t pah[4][4], pal[4][4];
#pragma unroll
        for (int kc2 = 0; kc2 < 4; kc2++) {
            const int n0i = 2*kc2, n1i = 2*kc2 + 1;
            float p[4][2] = {{sc[n0i][0], sc[n0i][1]}, {sc[n0i][2], sc[n0i][3]},
                             {sc[n1i][0], sc[n1i][1]}, {sc[n1i][2], sc[n1i][3]}};
#pragma unroll
            for (int a = 0; a < 4; a++) {
                uint32_t hp = bf16x2_pack(p[a][0], p[a][1]);
                float h0 = __uint_as_float(hp << 16);
                float h1 = __uint_as_float(hp & 0xFFFF0000u);
                pah[kc2][a] = hp;
                pal[kc2][a] = bf16x2_pack(p[a][0] - h0, p[a][1] - h1);
            }
        }

        // ---- O += P·V, 3 passes ----
#pragma unroll
        for (int d0 = 0; d0 < 8; d0++) {        // d chunks of 16
#pragma unroll
            for (int kc2 = 0; kc2 < 4; kc2++) {
                uint32_t addr = vbase + (kc2*16 + (lane & 15)) * AT_RS
                              + d0*32 + (lane >> 4) * 16;
                uint32_t rvh[4], rvl[4];
                LDSM4T(rvh, addr);
                LDSM4T(rvl, addr + AT_TSIZE);
                uint32_t b0h[2] = {rvh[0], rvh[1]}, b1h[2] = {rvh[2], rvh[3]};
                uint32_t b0l[2] = {rvl[0], rvl[1]}, b1l[2] = {rvl[2], rvl[3]};
                MMA16816(od[2*d0],   pah[kc2], b0h);
                MMA16816(od[2*d0],   pah[kc2], b0l);
                MMA16816(od[2*d0],   pal[kc2], b0h);
                MMA16816(od[2*d0+1], pah[kc2], b1h);
                MMA16816(od[2*d0+1], pah[kc2], b1l);
                MMA16816(od[2*d0+1], pal[kc2], b1h);
            }
        }

        __syncthreads();
        if (jt + 2 < njt) AT_ISSUE(jt + 2, st);
        else CP_COMMIT();          // keep group-count invariant for WAIT1
    }

    // ---- epilogue: O/l -> bf16 hi/lo ----
    const float i0 = 1.0f / l0, i1 = 1.0f / l1;
    const long long row0 = (long long)(b*NS + q0 + w*16 + (lane >> 2)) * ND + h * HD;
    const long long row1 = row0 + 8ll * ND;
#pragma unroll
    for (int nd = 0; nd < 16; nd++) {
        const int d = nd*8 + (lane & 3)*2;
        float v00 = od[nd][0]*i0, v01 = od[nd][1]*i0;
        float v10 = od[nd][2]*i1, v11 = od[nd][3]*i1;
        uint32_t h0 = bf16x2_pack(v00, v01);
        uint32_t h1 = bf16x2_pack(v10, v11);
        float h00 = __uint_as_float(h0 << 16), h01 = __uint_as_float(h0 & 0xFFFF0000u);
        float h10 = __uint_as_float(h1 << 16), h11 = __uint_as_float(h1 & 0xFFFF0000u);
        *(uint32_t*)&oh[row0 + d] = h0;
        *(uint32_t*)&oh[row1 + d] = h1;
        *(uint32_t*)&ol[row0 + d] = bf16x2_pack(v00 - h00, v01 - h01);
        *(uint32_t*)&ol[row1 + d] = bf16x2_pack(v10 - h10, v11 - h11);
    }
#undef AT_ISSUE
}

// ============================================================================
extern "C" void kernel_launch(void* const* d_in, const int* in_sizes, int n_in,
                              void* d_out, int out_size)
{
    (void)in_sizes; (void)n_in; (void)out_size;
    const float* queries = (const float*)d_in[0];
    const float* keys    = (const float*)d_in[1];
    const float* values  = (const float*)d_in[2];
    const float* Wq = (const float*)d_in[3];
    const float* bq = (const float*)d_in[4];
    const float* Wk = (const float*)d_in[5];
    const float* bk = (const float*)d_in[6];
    const float* Wv = (const float*)d_in[7];
    const float* bv = (const float*)d_in[8];
    const float* Wo = (const float*)d_in[9];
    const float* bo = (const float*)d_in[10];
    float* out = (float*)d_out;

    float *q, *k;
    __nv_bfloat16 *wth, *wtl, *ah, *al, *qh, *ql, *kh, *kl, *vh, *vl;
    cudaGetSymbolAddress((void**)&q,   g_q);
    cudaGetSymbolAddress((void**)&k,   g_k);
    cudaGetSymbolAddress((void**)&wth, g_wth);
    cudaGetSymbolAddress((void**)&wtl, g_wtl);
    cudaGetSymbolAddress((void**)&ah,  g_ah);
    cudaGetSymbolAddress((void**)&al,  g_al);
    cudaGetSymbolAddress((void**)&qh,  g_qh);
    cudaGetSymbolAddress((void**)&ql,  g_ql);
    cudaGetSymbolAddress((void**)&kh,  g_kh);
    cudaGetSymbolAddress((void**)&kl,  g_kl);
    cudaGetSymbolAddress((void**)&vh,  g_vh);
    cudaGetSymbolAddress((void**)&vl,  g_vl);

    cudaFuncSetAttribute(gemm_mma_kernel,
                         cudaFuncAttributeMaxDynamicSharedMemorySize, GM_SMEM);
    cudaFuncSetAttribute(attn_mma_kernel,
                         cudaFuncAttributeMaxDynamicSharedMemorySize, AT_SMEM);

    // ---- split + transpose weights ----
    const float* Ws[4] = {Wq, Wk, Wv, Wo};
    dim3 gw(ND/32, ND/32), bw(32, 8);
    for (int i = 0; i < 4; i++)
        split_w_kernel<<<gw, bw>>>(Ws[i], wth + (long long)i*ND*ND,
                                          wtl + (long long)i*ND*ND);

    const int nsplit = NM*ND/4/256;
    dim3 gtg(ND/128, NM/128);                  // (16, 32)

    // ---- projections ----
    split_a_kernel<<<nsplit, 256>>>(queries, ah, al);
    gemm_mma_kernel<<<gtg, 256, GM_SMEM>>>(ah, al, wth + 0ll*ND*ND, wtl + 0ll*ND*ND,
                                           bq, q, nullptr, nullptr);
    split_a_kernel<<<nsplit, 256>>>(keys, ah, al);
    gemm_mma_kernel<<<gtg, 256, GM_SMEM>>>(ah, al, wth + 1ll*ND*ND, wtl + 1ll*ND*ND,
                                           bk, k, nullptr, nullptr);
    split_a_kernel<<<nsplit, 256>>>(values, ah, al);
    gemm_mma_kernel<<<gtg, 256, GM_SMEM>>>(ah, al, wth + 2ll*ND*ND, wtl + 2ll*ND*ND,
                                           bv, nullptr, vh, vl);

    // ---- RoPE + split (scale folded into Q) ----
    int nrope = NM * NH * 64;
    rope_split_kernel<<<nrope/256, 256>>>(q, qh, ql, 0.08838834764831845f);
    rope_split_kernel<<<nrope/256, 256>>>(k, kh, kl, 1.0f);

    // ---- attention (writes bf16 hi/lo directly into ah/al) ----
    dim3 ga(NS/128, NH, NB);
    attn_mma_kernel<<<ga, 256, AT_SMEM>>>(qh, ql, kh, kl, vh, vl, ah, al);

    // ---- output projection ----
    gemm_mma_kernel<<<gtg, 256, GM_SMEM>>>(ah, al, wth + 3ll*ND*ND, wtl + 3ll*ND*ND,
                                           bo, out, nullptr, nullptr);
}

// round 5
// speedup vs baseline: 1.7079x; 1.0001x over previous
#include <cuda_runtime.h>
#include <cuda_bf16.h>
#include <cstdint>
#include <math.h>

#define NB 2
#define NS 2048
#define ND 2048
#define NH 16
#define HD 128
#define NM (NB*NS)   // 4096 rows

// ---- scratch (static device arrays; no allocation allowed) ----
__device__ float g_q[NM*ND];                     // fp32 Q proj (pre-rope)
__device__ float g_k[NM*ND];                     // fp32 K proj (pre-rope)
__device__ __nv_bfloat16 g_wth[4ll*ND*ND];       // W^T hi, [N][K] K-major
__device__ __nv_bfloat16 g_wtl[4ll*ND*ND];       // W^T lo
__device__ __nv_bfloat16 g_ah[(long long)NM*ND]; // activation hi (gemm A / att out)
__device__ __nv_bfloat16 g_al[(long long)NM*ND]; // activation lo
__device__ __nv_bfloat16 g_qh[(long long)NM*ND]; // roped Q hi (scaled)
__device__ __nv_bfloat16 g_ql[(long long)NM*ND];
__device__ __nv_bfloat16 g_kh[(long long)NM*ND]; // roped K hi
__device__ __nv_bfloat16 g_kl[(long long)NM*ND];
__device__ __nv_bfloat16 g_vh[(long long)NM*ND]; // V proj hi
__device__ __nv_bfloat16 g_vl[(long long)NM*ND];

__device__ __forceinline__ uint32_t smem_u32(const void* p) {
    uint32_t a;
    asm("{ .reg .u64 t; cvta.to.shared.u64 t, %1; cvt.u32.u64 %0, t; }"
        : "=r"(a) : "l"(p));
    return a;
}

// ---- base-target tensor core primitives (sm_80-class, valid on compute_103) ----
#define LDSM4(r, addr) \
    asm volatile("ldmatrix.sync.aligned.m8n8.x4.shared.b16 {%0,%1,%2,%3}, [%4];" \
        : "=r"((r)[0]), "=r"((r)[1]), "=r"((r)[2]), "=r"((r)[3]) : "r"(addr))

#define LDSM4T(r, addr) \
    asm volatile("ldmatrix.sync.aligned.m8n8.x4.trans.shared.b16 {%0,%1,%2,%3}, [%4];" \
        : "=r"((r)[0]), "=r"((r)[1]), "=r"((r)[2]), "=r"((r)[3]) : "r"(addr))

#define MMA16816(d, a, b) \
    asm volatile("mma.sync.aligned.m16n8k16.row.col.f32.bf16.bf16.f32 " \
        "{%0,%1,%2,%3}, {%4,%5,%6,%7}, {%8,%9}, {%0,%1,%2,%3};" \
        : "+f"((d)[0]), "+f"((d)[1]), "+f"((d)[2]), "+f"((d)[3]) \
        : "r"((a)[0]), "r"((a)[1]), "r"((a)[2]), "r"((a)[3]), \
          "r"((b)[0]), "r"((b)[1]))

#define CP_ASYNC16(dst, src) \
    asm volatile("cp.async.cg.shared.global [%0], [%1], 16;" \
                 :: "r"(dst), "l"(src) : "memory")
#define CP_COMMIT()  asm volatile("cp.async.commit_group;" ::: "memory")
#define CP_WAIT1()   asm volatile("cp.async.wait_group 1;" ::: "memory")
#define CP_WAIT0()   asm volatile("cp.async.wait_group 0;" ::: "memory")

// pack two f32 into bf16x2 (x -> low half)
__device__ __forceinline__ uint32_t bf16x2_pack(float lo, float hi) {
    __nv_bfloat162 v = __floats2bfloat162_rn(lo, hi);
    return *reinterpret_cast<uint32_t*>(&v);
}

// ============================================================================
// Preprocessing: split fp32 into bf16 hi/lo
// ============================================================================
__global__ void split_a_kernel(const float* __restrict__ X,
                               __nv_bfloat16* __restrict__ hi,
                               __nv_bfloat16* __restrict__ lo)
{
    long long idx = (long long)(blockIdx.x * blockDim.x + threadIdx.x) * 4;
    float4 x = *(const float4*)(X + idx);
    float v[4] = {x.x, x.y, x.z, x.w};
    __nv_bfloat16 h[4], l[4];
#pragma unroll
    for (int j = 0; j < 4; j++) {
        h[j] = __float2bfloat16(v[j]);
        l[j] = __float2bfloat16(v[j] - __bfloat162float(h[j]));
    }
    *(__nv_bfloat162*)(hi + idx)     = __nv_bfloat162(h[0], h[1]);
    *(__nv_bfloat162*)(hi + idx + 2) = __nv_bfloat162(h[2], h[3]);
    *(__nv_bfloat162*)(lo + idx)     = __nv_bfloat162(l[0], l[1]);
    *(__nv_bfloat162*)(lo + idx + 2) = __nv_bfloat162(l[2], l[3]);
}

// W[K][N] fp32 -> Wt_hi/Wt_lo[N][K] bf16 (transpose + split)
__global__ void split_w_kernel(const float* __restrict__ W,
                               __nv_bfloat16* __restrict__ hi,
                               __nv_bfloat16* __restrict__ lo)
{
    __shared__ float t[32][33];
    int n0 = blockIdx.x * 32, k0 = blockIdx.y * 32;
    int tx = threadIdx.x, ty = threadIdx.y;
    for (int r = ty; r < 32; r += 8)
        t[r][tx] = W[(long long)(k0 + r) * ND + n0 + tx];
    __syncthreads();
    for (int r = ty; r < 32; r += 8) {
        float x = t[tx][r];   // = W[k0+tx][n0+r]
        __nv_bfloat16 h = __float2bfloat16(x);
        __nv_bfloat16 l = __float2bfloat16(x - __bfloat162float(h));
        long long o = (long long)(n0 + r) * ND + k0 + tx;
        hi[o] = h; lo[o] = l;
    }
}

// ============================================================================
// Split-bf16 GEMM on mma.sync: C = (Ah+Al)@(Bh+Bl)^T + bias
// Outputs: fp32 C (if non-null) and/or bf16 hi/lo (if non-null).
// Restructured for <=128 regs -> 2 CTAs/SM (tensor pipe stays fed across
// barriers/waits via the partner CTA).
// ============================================================================
#define GM_STAGE 40960                    // 4 matrices * 128 rows * 80B
#define GM_SMEM  (2*GM_STAGE)             // 81920

__global__ __launch_bounds__(256, 2)
void gemm_mma_kernel(const __nv_bfloat16* __restrict__ Ah,
                     const __nv_bfloat16* __restrict__ Al,
                     const __nv_bfloat16* __restrict__ Bh,
                     const __nv_bfloat16* __restrict__ Bl,
                     const float* __restrict__ bias,
                     float* __restrict__ C,
                     __nv_bfloat16* __restrict__ Chi,
                     __nv_bfloat16* __restrict__ Clo)
{
    extern __shared__ char dsm[];
    const uint32_t sb = smem_u32(dsm);
    const int tid  = threadIdx.x;
    const int lane = tid & 31, wid = tid >> 5;
    const int wm = wid & 1, wn = wid >> 1;      // warp tile: m 64, n 32
    const int m0 = blockIdx.y * 128, n0 = blockIdx.x * 128;

    const int lrow = tid >> 1;
    const int lc   = (tid & 1) * 16;
    const __nv_bfloat16* gsrc[4];
    gsrc[0] = Ah + (long long)(m0 + lrow) * ND + lc;
    gsrc[1] = Al + (long long)(m0 + lrow) * ND + lc;
    gsrc[2] = Bh + (long long)(n0 + lrow) * ND + lc;
    gsrc[3] = Bl + (long long)(n0 + lrow) * ND + lc;
    const uint32_t sdst0 = sb + lrow * 80 + (tid & 1) * 32;

    float acc[4][4][4];
#pragma unroll
    for (int i = 0; i < 4; i++)
#pragma unroll
        for (int j = 0; j < 4; j++)
#pragma unroll
            for (int c = 0; c < 4; c++) acc[i][j][c] = 0.0f;

#define GM_ISSUE(ch, stage) do { \
        uint32_t s0 = sdst0 + (stage) * GM_STAGE; \
        _Pragma("unroll") \
        for (int m = 0; m < 4; m++) { \
            const __nv_bfloat16* g = gsrc[m] + (ch) * 32; \
            uint32_t d = s0 + m * 10240; \
            CP_ASYNC16(d, g); \
            CP_ASYNC16(d + 16, g + 8); \
        } \
        CP_COMMIT(); \
    } while (0)

    GM_ISSUE(0, 0);
    GM_ISSUE(1, 1);

    for (int ch = 0; ch < 64; ch++) {
        const int st = ch & 1;
        CP_WAIT1();
        __syncthreads();
        const uint32_t abase = sb + st * GM_STAGE + (wm * 64) * 80
                             + (lane & 15) * 80 + (lane >> 4) * 16;
        const uint32_t bbase = sb + st * GM_STAGE + 20480 + (wn * 32) * 80
                             + (lane & 15) * 80 + (lane >> 4) * 16;
#pragma unroll
        for (int kk = 0; kk < 32; kk += 16) {
            // B fragments for this kk (held across the mt loop)
            uint32_t bh[4][2], bl[4][2];
#pragma unroll
            for (int np = 0; np < 2; np++) {
                uint32_t addr = bbase + np * 16 * 80 + kk * 2;
                uint32_t r[4], s[4];
                LDSM4(r, addr);
                LDSM4(s, addr + 10240);
                bh[np*2+0][0] = r[0]; bh[np*2+0][1] = r[2];
                bh[np*2+1][0] = r[1]; bh[np*2+1][1] = r[3];
                bl[np*2+0][0] = s[0]; bl[np*2+0][1] = s[2];
                bl[np*2+1][0] = s[1]; bl[np*2+1][1] = s[3];
            }
            // A fragments loaded per mt (keeps live regs low)
#pragma unroll
            for (int mt = 0; mt < 4; mt++) {
                uint32_t ah[4], al[4];
                uint32_t addr = abase + mt * 16 * 80 + kk * 2;
                LDSM4(ah, addr);
                LDSM4(al, addr + 10240);
#pragma unroll
                for (int nt = 0; nt < 4; nt++) {
                    MMA16816(acc[mt][nt], ah, bh[nt]);
                    MMA16816(acc[mt][nt], ah, bl[nt]);
                    MMA16816(acc[mt][nt], al, bh[nt]);
                }
            }
        }
        __syncthreads();
        if (ch + 2 < 64) GM_ISSUE(ch + 2, st);
        else CP_COMMIT();          // keep group-count invariant for WAIT1
    }

    // ---- epilogue ----
    const int r0 = m0 + wm * 64 + (lane >> 2);
    const int c0 = n0 + wn * 32 + (lane & 3) * 2;
#pragma unroll
    for (int nt = 0; nt < 4; nt++) {
        const int c = c0 + nt * 8;
        const float b0 = bias[c], b1 = bias[c + 1];
#pragma unroll
        for (int mt = 0; mt < 4; mt++) {
            const int r = r0 + mt * 16;
            float v00 = acc[mt][nt][0] + b0, v01 = acc[mt][nt][1] + b1;
            float v10 = acc[mt][nt][2] + b0, v11 = acc[mt][nt][3] + b1;
            if (C) {
                *(float2*)&C[(long long)r * ND + c]       = make_float2(v00, v01);
                *(float2*)&C[(long long)(r + 8) * ND + c] = make_float2(v10, v11);
            }
            if (Chi) {
                uint32_t h0 = bf16x2_pack(v00, v01);
                uint32_t h1 = bf16x2_pack(v10, v11);
                float h00 = __uint_as_float(h0 << 16), h01 = __uint_as_float(h0 & 0xFFFF0000u);
                float h10 = __uint_as_float(h1 << 16), h11 = __uint_as_float(h1 & 0xFFFF0000u);
                uint32_t l0 = bf16x2_pack(v00 - h00, v01 - h01);
                uint32_t l1 = bf16x2_pack(v10 - h10, v11 - h11);
                *(uint32_t*)&Chi[(long long)r * ND + c]       = h0;
                *(uint32_t*)&Chi[(long long)(r + 8) * ND + c] = h1;
                *(uint32_t*)&Clo[(long long)r * ND + c]       = l0;
                *(uint32_t*)&Clo[(long long)(r + 8) * ND + c] = l1;
            }
        }
    }
#undef GM_ISSUE
}

// ============================================================================
// RoPE + split: read fp32 proj, rotate, scale, write bf16 hi/lo
// ============================================================================
__global__ void rope_split_kernel(const float* __restrict__ X,
                                  __nv_bfloat16* __restrict__ hi,
                                  __nv_bfloat16* __restrict__ lo,
                                  float scale)
{
    int idx = blockIdx.x * blockDim.x + threadIdx.x;  // NM * NH * 64
    int i   = idx & 63;
    int h   = (idx >> 6) & (NH - 1);
    int row = idx >> 10;
    int s   = row & (NS - 1);
    float invf = powf(10000.0f, -(float)i / 64.0f);
    float ang = (float)s * invf;
    float sn, cs;
    sincosf(ang, &sn, &cs);
    long long off = (long long)row * ND + h * HD + i;
    float x1 = X[off], x2 = X[off + 64];
    float o1 = (x1 * cs - x2 * sn) * scale;
    float o2 = (x2 * cs + x1 * sn) * scale;
    __nv_bfloat16 h1 = __float2bfloat16(o1);
    __nv_bfloat16 h2 = __float2bfloat16(o2);
    hi[off]      = h1;
    hi[off + 64] = h2;
    lo[off]      = __float2bfloat16(o1 - __bfloat162float(h1));
    lo[off + 64] = __float2bfloat16(o2 - __bfloat162float(h2));
}

// ============================================================================
// Causal flash attention on mma.sync, split-bf16 3-pass both GEMMs.
// CTA: (b, h, 128-q tile); 8 warps, each owns 16 q rows.
// K/V tiles of 64 keys, cp.async double-buffered.
// ============================================================================
#define AT_RS    272                       // row stride bytes (136 bf16)
#define AT_TSIZE (64*AT_RS)                // 17408 per matrix tile
#define AT_STAGE (4*AT_TSIZE)              // 69632: Kh,Kl,Vh,Vl
#define AT_SMEM  (2*AT_STAGE)              // 139264

__global__ __launch_bounds__(256)
void attn_mma_kernel(const __nv_bfloat16* __restrict__ qh,
                     const __nv_bfloat16* __restrict__ ql,
                     const __nv_bfloat16* __restrict__ kh,
                     const __nv_bfloat16* __restrict__ kl,
                     const __nv_bfloat16* __restrict__ vh,
                     const __nv_bfloat16* __restrict__ vl,
                     __nv_bfloat16* __restrict__ oh,
                     __nv_bfloat16* __restrict__ ol)
{
    extern __shared__ char dsm[];
    const uint32_t sb = smem_u32(dsm);
    const int tid  = threadIdx.x;
    const int lane = tid & 31, w = tid >> 5;
    const int qt = (NS/128 - 1) - blockIdx.x;   // heavy tiles first
    const int h  = blockIdx.y;
    const int b  = blockIdx.z;
    const int q0 = qt * 128;
    const long long gbase = (long long)b * NS * ND + h * HD;

    // ---- stage Q (hi then lo) into stage-0 region, 256B payload/row ----
    {
        int r = tid & 127;
        const __nv_bfloat16* src = ((tid < 128) ? qh : ql) + gbase + (long long)(q0 + r) * ND;
        uint32_t dst = sb + ((tid < 128) ? 0 : 128*AT_RS) + r * AT_RS;
#pragma unroll
        for (int c = 0; c < 16; c++) CP_ASYNC16(dst + c*16, src + c*8);
        CP_COMMIT();
        CP_WAIT0();
        __syncthreads();
    }

    // ---- Q fragments to registers (8 k16-chunks, hi+lo) ----
    uint32_t qfh[8][4], qfl[8][4];
    {
        uint32_t qaddr = sb + (w*16 + (lane & 15)) * AT_RS + (lane >> 4) * 16;
#pragma unroll
        for (int kc = 0; kc < 8; kc++) {
            LDSM4(qfh[kc], qaddr + kc*32);
            LDSM4(qfl[kc], qaddr + kc*32 + 128*AT_RS);
        }
    }
    __syncthreads();   // done reading stage-0 region

    // ---- K/V tile loader: 4 matrices x 64 rows, one row per thread ----
    const __nv_bfloat16* kvsrc;
    {
        const __nv_bfloat16* s4[4] = {kh, kl, vh, vl};
        kvsrc = s4[tid >> 6] + gbase + (long long)(tid & 63) * ND;
    }
    const uint32_t kvdst = sb + (tid >> 6) * AT_TSIZE + (tid & 63) * AT_RS;

#define AT_ISSUE(jt, st) do { \
        const __nv_bfloat16* g = kvsrc + (long long)(jt) * 64 * ND; \
        uint32_t d = kvdst + (st) * AT_STAGE; \
        _Pragma("unroll") \
        for (int c = 0; c < 16; c++) CP_ASYNC16(d + c*16, g + c*8); \
        CP_COMMIT(); \
    } while (0)

    const int njt = 2*qt + 2;
    AT_ISSUE(0, 0);
    AT_ISSUE(1, 1);

    float m0v = -1e30f, m1v = -1e30f, l0 = 0.0f, l1 = 0.0f;
    float od[16][4];
#pragma unroll
    for (int nd = 0; nd < 16; nd++)
#pragma unroll
        for (int c = 0; c < 4; c++) od[nd][c] = 0.0f;

    for (int jt = 0; jt < njt; jt++) {
        const int st = jt & 1;
        CP_WAIT1();
        __syncthreads();
        const uint32_t kbase = sb + st * AT_STAGE;
        const uint32_t vbase = kbase + 2 * AT_TSIZE;

        // ---- S = Q·K^T (16 x 64 per warp), 3 passes ----
        float sc[8][4];
#pragma unroll
        for (int n = 0; n < 8; n++)
#pragma unroll
            for (int c = 0; c < 4; c++) sc[n][c] = 0.0f;

#pragma unroll
        for (int kc = 0; kc < 8; kc++) {
#pragma unroll
            for (int ng = 0; ng < 4; ng++) {
                uint32_t addr = kbase + (ng*16 + (lane & 15)) * AT_RS
                              + kc*32 + (lane >> 4) * 16;
                uint32_t rh[4], rl[4];
                LDSM4(rh, addr);
                LDSM4(rl, addr + AT_TSIZE);
                uint32_t b0h[2] = {rh[0], rh[2]}, b1h[2] = {rh[1], rh[3]};
                uint32_t b0l[2] = {rl[0], rl[2]}, b1l[2] = {rl[1], rl[3]};
                MMA16816(sc[2*ng],   qfh[kc], b0h);
                MMA16816(sc[2*ng],   qfh[kc], b0l);
                MMA16816(sc[2*ng],   qfl[kc], b0h);
                MMA16816(sc[2*ng+1], qfh[kc], b1h);
                MMA16816(sc[2*ng+1], qfh[kc], b1l);
                MMA16816(sc[2*ng+1], qfl[kc], b1h);
            }
        }

        // ---- causal mask (only the two diagonal k-tiles) ----
        if (jt >= njt - 2) {
            const int qrow = q0 + w*16 + (lane >> 2);
            const int kc0  = jt*64 + (lane & 3)*2;
#pragma unroll
            for (int n = 0; n < 8; n++) {
                int kcol = kc0 + n*8;
                if (kcol     > qrow)     sc[n][0] = -1e30f;
                if (kcol + 1 > qrow)     sc[n][1] = -1e30f;
                if (kcol     > qrow + 8) sc[n][2] = -1e30f;
                if (kcol + 1 > qrow + 8) sc[n][3] = -1e30f;
            }
        }

        // ---- online softmax ----
        float mx0 = -1e30f, mx1 = -1e30f;
#pragma unroll
        for (int n = 0; n < 8; n++) {
            mx0 = fmaxf(mx0, fmaxf(sc[n][0], sc[n][1]));
            mx1 = fmaxf(mx1, fmaxf(sc[n][2], sc[n][3]));
        }
        mx0 = fmaxf(mx0, __shfl_xor_sync(0xffffffffu, mx0, 1));
        mx0 = fmaxf(mx0, __shfl_xor_sync(0xffffffffu, mx0, 2));
        mx1 = fmaxf(mx1, __shfl_xor_sync(0xffffffffu, mx1, 1));
        mx1 = fmaxf(mx1, __shfl_xor_sync(0xffffffffu, mx1, 2));
        float mn0 = fmaxf(m0v, mx0), mn1 = fmaxf(m1v, mx1);
        float corr0 = __expf(m0v - mn0), corr1 = __expf(m1v - mn1);
        float ps0 = 0.0f, ps1 = 0.0f;
#pragma unroll
        for (int n = 0; n < 8; n++) {
            sc[n][0] = __expf(sc[n][0] - mn0);
            sc[n][1] = __expf(sc[n][1] - mn0);
            sc[n][2] = __expf(sc[n][2] - mn1);
            sc[n][3] = __expf(sc[n][3] - mn1);
            ps0 += sc[n][0] + sc[n][1];
            ps1 += sc[n][2] + sc[n][3];
        }
        ps0 += __shfl_xor_sync(0xffffffffu, ps0, 1);
        ps0 += __shfl_xor_sync(0xffffffffu, ps0, 2);
        ps1 += __shfl_xor_sync(0xffffffffu, ps1, 1);
        ps1 += __shfl_xor_sync(0xffffffffu, ps1, 2);
        l0 = l0 * corr0 + ps0;  m0v = mn0;
        l1 = l1 * corr1 + ps1;  m1v = mn1;
#pragma unroll
        for (int nd = 0; nd < 16; nd++) {
            od[nd][0] *= corr0; od[nd][1] *= corr0;
            od[nd][2] *= corr1; od[nd][3] *= corr1;
        }

        // ---- repack P (C-frags) into A-frags, bf16 hi/lo ----
        uint32_t pah[4][4], pal[4][4];
#pragma unroll
        for (int kc2 = 0; kc2 < 4; kc2++) {
            const int n0i = 2*kc2, n1i = 2*kc2 + 1;
            float p[4][2] = {{sc[n0i][0], sc[n0i][1]}, {sc[n0i][2], sc[n0i][3]},
                             {sc[n1i][0], sc[n1i][1]}, {sc[n1i][2], sc[n1i][3]}};
#pragma unroll
            for (int a = 0; a < 4; a++) {
                uint32_t hp = bf16x2_pack(p[a][0], p[a][1]);
                float h0 = __uint_as_float(hp << 16);
                float h1 = __uint_as_float(hp & 0xFFFF0000u);
                pah[kc2][a] = hp;
                pal[kc2][a] = bf16x2_pack(p[a][0] - h0, p[a][1] - h1);
            }
        }

        // ---- O += P·V, 3 passes ----
#pragma unroll
        for (int d0 = 0; d0 < 8; d0++) {        // d chunks of 16
#pragma unroll
            for (int kc2 = 0; kc2 < 4; kc2++) {
                uint32_t addr = vbase + (kc2*16 + (lane & 15)) * AT_RS
                              + d0*32 + (lane >> 4) * 16;
                uint32_t rvh[4], rvl[4];
                LDSM4T(rvh, addr);
                LDSM4T(rvl, addr + AT_TSIZE);
                uint32_t b0h[2] = {rvh[0], rvh[1]}, b1h[2] = {rvh[2], rvh[3]};
                uint32_t b0l[2] = {rvl[0], rvl[1]}, b1l[2] = {rvl[2], rvl[3]};
                MMA16816(od[2*d0],   pah[kc2], b0h);
                MMA16816(od[2*d0],   pah[kc2], b0l);
                MMA16816(od[2*d0],   pal[kc2], b0h);
                MMA16816(od[2*d0+1], pah[kc2], b1h);
                MMA16816(od[2*d0+1], pah[kc2], b1l);
                MMA16816(od[2*d0+1], pal[kc2], b1h);
            }
        }

        __syncthreads();
        if (jt + 2 < njt) AT_ISSUE(jt + 2, st);
        else CP_COMMIT();          // keep group-count invariant for WAIT1
    }

    // ---- epilogue: O/l -> bf16 hi/lo ----
    const float i0 = 1.0f / l0, i1 = 1.0f / l1;
    const long long row0 = (long long)(b*NS + q0 + w*16 + (lane >> 2)) * ND + h * HD;
    const long long row1 = row0 + 8ll * ND;
#pragma unroll
    for (int nd = 0; nd < 16; nd++) {
        const int d = nd*8 + (lane & 3)*2;
        float v00 = od[nd][0]*i0, v01 = od[nd][1]*i0;
        float v10 = od[nd][2]*i1, v11 = od[nd][3]*i1;
        uint32_t h0 = bf16x2_pack(v00, v01);
        uint32_t h1 = bf16x2_pack(v10, v11);
        float h00 = __uint_as_float(h0 << 16), h01 = __uint_as_float(h0 & 0xFFFF0000u);
        float h10 = __uint_as_float(h1 << 16), h11 = __uint_as_float(h1 & 0xFFFF0000u);
        *(uint32_t*)&oh[row0 + d] = h0;
        *(uint32_t*)&oh[row1 + d] = h1;
        *(uint32_t*)&ol[row0 + d] = bf16x2_pack(v00 - h00, v01 - h01);
        *(uint32_t*)&ol[row1 + d] = bf16x2_pack(v10 - h10, v11 - h11);
    }
#undef AT_ISSUE
}

// ============================================================================
extern "C" void kernel_launch(void* const* d_in, const int* in_sizes, int n_in,
                              void* d_out, int out_size)
{
    (void)in_sizes; (void)n_in; (void)out_size;
    const float* queries = (const float*)d_in[0];
    const float* keys    = (const float*)d_in[1];
    const float* values  = (const float*)d_in[2];
    const float* Wq = (const float*)d_in[3];
    const float* bq = (const float*)d_in[4];
    const float* Wk = (const float*)d_in[5];
    const float* bk = (const float*)d_in[6];
    const float* Wv = (const float*)d_in[7];
    const float* bv = (const float*)d_in[8];
    const float* Wo = (const float*)d_in[9];
    const float* bo = (const float*)d_in[10];
    float* out = (float*)d_out;

    float *q, *k;
    __nv_bfloat16 *wth, *wtl, *ah, *al, *qh, *ql, *kh, *kl, *vh, *vl;
    cudaGetSymbolAddress((void**)&q,   g_q);
    cudaGetSymbolAddress((void**)&k,   g_k);
    cudaGetSymbolAddress((void**)&wth, g_wth);
    cudaGetSymbolAddress((void**)&wtl, g_wtl);
    cudaGetSymbolAddress((void**)&ah,  g_ah);
    cudaGetSymbolAddress((void**)&al,  g_al);
    cudaGetSymbolAddress((void**)&qh,  g_qh);
    cudaGetSymbolAddress((void**)&ql,  g_ql);
    cudaGetSymbolAddress((void**)&kh,  g_kh);
    cudaGetSymbolAddress((void**)&kl,  g_kl);
    cudaGetSymbolAddress((void**)&vh,  g_vh);
    cudaGetSymbolAddress((void**)&vl,  g_vl);

    cudaFuncSetAttribute(gemm_mma_kernel,
                         cudaFuncAttributeMaxDynamicSharedMemorySize, GM_SMEM);
    cudaFuncSetAttribute(attn_mma_kernel,
                         cudaFuncAttributeMaxDynamicSharedMemorySize, AT_SMEM);

    // ---- split + transpose weights ----
    const float* Ws[4] = {Wq, Wk, Wv, Wo};
    dim3 gw(ND/32, ND/32), bw(32, 8);
    for (int i = 0; i < 4; i++)
        split_w_kernel<<<gw, bw>>>(Ws[i], wth + (long long)i*ND*ND,
                                          wtl + (long long)i*ND*ND);

    const int nsplit = NM*ND/4/256;
    dim3 gtg(ND/128, NM/128);                  // (16, 32)

    // ---- projections ----
    split_a_kernel<<<nsplit, 256>>>(queries, ah, al);
    gemm_mma_kernel<<<gtg, 256, GM_SMEM>>>(ah, al, wth + 0ll*ND*ND, wtl + 0ll*ND*ND,
                                           bq, q, nullptr, nullptr);
    split_a_kernel<<<nsplit, 256>>>(keys, ah, al);
    gemm_mma_kernel<<<gtg, 256, GM_SMEM>>>(ah, al, wth + 1ll*ND*ND, wtl + 1ll*ND*ND,
                                           bk, k, nullptr, nullptr);
    split_a_kernel<<<nsplit, 256>>>(values, ah, al);
    gemm_mma_kernel<<<gtg, 256, GM_SMEM>>>(ah, al, wth + 2ll*ND*ND, wtl + 2ll*ND*ND,
                                           bv, nullptr, vh, vl);

    // ---- RoPE + split (scale folded into Q) ----
    int nrope = NM * NH * 64;
    rope_split_kernel<<<nrope/256, 256>>>(q, qh, ql, 0.08838834764831845f);
    rope_split_kernel<<<nrope/256, 256>>>(k, kh, kl, 1.0f);

    // ---- attention (writes bf16 hi/lo directly into ah/al) ----
    dim3 ga(NS/128, NH, NB);
    attn_mma_kernel<<<ga, 256, AT_SMEM>>>(qh, ql, kh, kl, vh, vl, ah, al);

    // ---- output projection ----
    gemm_mma_kernel<<<gtg, 256, GM_SMEM>>>(ah, al, wth + 3ll*ND*ND, wtl + 3ll*ND*ND,
                                           bo, out, nullptr, nullptr);
}